// round 16
// baseline (speedup 1.0000x reference)
#include <cuda_runtime.h>
#include <cuda_bf16.h>
#include <cstdint>
#include <cstddef>

// Problem constants: B=8, T=1024, D=1024, N=256, L=768, H=16, hd=64, TE=2048

// ================= helpers =================
__device__ __forceinline__ uint32_t smem_u32(const void* p) {
    uint32_t a;
    asm("{ .reg .u64 t; cvta.to.shared.u64 t, %1; cvt.u32.u64 %0, t; }" : "=r"(a) : "l"(p));
    return a;
}
#define CP_ASYNC16(smem, gptr) \
    asm volatile("cp.async.cg.shared.global [%0], [%1], 16;" :: "r"(smem), "l"(gptr))
#define CP_ASYNC_COMMIT() asm volatile("cp.async.commit_group;" ::: "memory")

__device__ __forceinline__ void ldsm_x4(uint32_t& r0, uint32_t& r1, uint32_t& r2, uint32_t& r3,
                                        uint32_t addr) {
    asm volatile("ldmatrix.sync.aligned.m8n8.x4.shared.b16 {%0,%1,%2,%3}, [%4];"
                 : "=r"(r0), "=r"(r1), "=r"(r2), "=r"(r3) : "r"(addr));
}
__device__ __forceinline__ void ldsm_x4_t(uint32_t& r0, uint32_t& r1, uint32_t& r2, uint32_t& r3,
                                          uint32_t addr) {
    asm volatile("ldmatrix.sync.aligned.m8n8.x4.trans.shared.b16 {%0,%1,%2,%3}, [%4];"
                 : "=r"(r0), "=r"(r1), "=r"(r2), "=r"(r3) : "r"(addr));
}
__device__ __forceinline__ void mma16816(float* d, const uint32_t* a, const uint32_t* b) {
    asm volatile("mma.sync.aligned.m16n8k16.row.col.f32.bf16.bf16.f32 "
                 "{%0,%1,%2,%3}, {%4,%5,%6,%7}, {%8,%9}, {%0,%1,%2,%3};"
                 : "+f"(d[0]), "+f"(d[1]), "+f"(d[2]), "+f"(d[3])
                 : "r"(a[0]), "r"(a[1]), "r"(a[2]), "r"(a[3]), "r"(b[0]), "r"(b[1]));
}
__device__ __forceinline__ uint32_t pack_bf16x2(float a, float b) {
    __nv_bfloat162 h = __floats2bfloat162_rn(a, b);
    return *(uint32_t*)&h;
}
__device__ __forceinline__ float fast_silu(float h) {
    return __fdividef(h, 1.f + __expf(-h));
}

// ================= scratch (device globals) =================
__device__ float g_embo[8u*2048u];
__device__ float g_embp[8u*8u*2048u];          // split-K partials [ky][b][j]
__device__ int   g_flags[768];                 // per-gemm-tile completion flags
__device__ int   g_mod_flag[1024];             // per-8-row modulate group done
__device__ __nv_bfloat16 g_yh [8192u*1024u];   // attn out bf16
__device__ __nv_bfloat16 g_xnh[8192u*1024u];   // LN(x) bf16
__device__ __nv_bfloat16 g_xfh[2048u*768u];    // LN(xf) bf16
__device__ __nv_bfloat16 g_qh [8192u*1024u];
__device__ __nv_bfloat16 g_kh [2048u*1024u];
__device__ __nv_bfloat16 g_vh [2048u*1024u];
__device__ __nv_bfloat16 g_hnh[8192u*1024u];
__device__ __nv_bfloat16 g_wq [1024u*1024u];   // W^T bf16 [N,K]
__device__ __nv_bfloat16 g_wk [1024u*768u];
__device__ __nv_bfloat16 g_wv [1024u*768u];
__device__ __nv_bfloat16 g_wo [1024u*1024u];

// ================= fused preprocess: LN(x), LN(xf), 4x weight transpose, emb split-K =================
__global__ void __launch_bounds__(256) preprocess_kernel(
    const float* __restrict__ x,  const float* __restrict__ ln_g, const float* __restrict__ ln_b,
    const float* __restrict__ xf, const float* __restrict__ cg,   const float* __restrict__ cb,
    const float* __restrict__ Wq, const float* __restrict__ Wk,
    const float* __restrict__ Wv, const float* __restrict__ Wo,
    const float* __restrict__ emb, const float* __restrict__ Wemb) {
    __shared__ float sh[2200];
    int blk = blockIdx.x;
    int tid = threadIdx.x;

    if (blk == 0) {
        // reset sync state for this run
        for (int i = tid; i < 768; i += 256) g_flags[i] = 0;
        for (int i = tid; i < 1024; i += 256) g_mod_flag[i] = 0;
    }

    if (blk < 10240) {
        // ---------- LayerNorm (vectorized) ----------
        int row = blk;
        const float* X; const float* gam; const float* bet; __nv_bfloat16* O; int Wd;
        if (row < 8192) { X = x; gam = ln_g; bet = ln_b; O = g_xnh; Wd = 1024; }
        else { row -= 8192; X = xf; gam = cg; bet = cb; O = g_xfh; Wd = 768; }
        const float* xr = X + (size_t)row * Wd;
        int i0 = tid * 4;
        bool act = i0 < Wd;
        float4 v4 = act ? *(const float4*)(xr + i0) : make_float4(0.f, 0.f, 0.f, 0.f);
        float sum = v4.x + v4.y + v4.z + v4.w;
        float sq  = v4.x * v4.x + v4.y * v4.y + v4.z * v4.z + v4.w * v4.w;
        #pragma unroll
        for (int o = 16; o; o >>= 1) {
            sum += __shfl_xor_sync(0xffffffffu, sum, o);
            sq  += __shfl_xor_sync(0xffffffffu, sq,  o);
        }
        int w = tid >> 5, l = tid & 31;
        if (l == 0) { sh[w] = sum; sh[8 + w] = sq; }
        __syncthreads();
        if (tid == 0) {
            float ts = 0.f, tq = 0.f;
            for (int i = 0; i < 8; i++) { ts += sh[i]; tq += sh[8 + i]; }
            float mean = ts / Wd;
            float var = tq / Wd - mean * mean;
            sh[16] = mean;
            sh[17] = rsqrtf(var + 1e-5f);
        }
        __syncthreads();
        if (act) {
            float mean = sh[16], inv = sh[17];
            float4 gg = *(const float4*)(gam + i0);
            float4 bb = *(const float4*)(bet + i0);
            uint2 o2;
            o2.x = pack_bf16x2((v4.x - mean) * inv * gg.x + bb.x,
                               (v4.y - mean) * inv * gg.y + bb.y);
            o2.y = pack_bf16x2((v4.z - mean) * inv * gg.z + bb.z,
                               (v4.w - mean) * inv * gg.w + bb.w);
            *(uint2*)(O + (size_t)row * Wd + i0) = o2;
        }
    } else if (blk < 13824) {
        // ---------- weight transpose W[K,N] -> T[N,K] bf16 ----------
        int idx = blk - 10240;
        const float* W; __nv_bfloat16* Th; int K, kt;
        if (idx < 1024)      { W = Wq; Th = g_wq; K = 1024; kt = 32; }
        else if (idx < 1792) { W = Wk; Th = g_wk; K = 768;  kt = 24; idx -= 1024; }
        else if (idx < 2560) { W = Wv; Th = g_wv; K = 768;  kt = 24; idx -= 1792; }
        else                 { W = Wo; Th = g_wo; K = 1024; kt = 32; idx -= 2560; }
        int k0 = (idx % kt) * 32, n0 = (idx / kt) * 32;
        float (*t)[33] = (float(*)[33])sh;
        int tx = tid & 31, ty = tid >> 5;
        #pragma unroll
        for (int r = ty; r < 32; r += 8)
            t[r][tx] = W[(size_t)(k0 + r) * 1024 + n0 + tx];
        __syncthreads();
        #pragma unroll
        for (int r = ty; r < 32; r += 8)
            Th[(size_t)(n0 + r) * K + k0 + tx] = __float2bfloat16(t[tx][r]);
    } else {
        // ---------- silu(emb) @ Wemb split-K partials ----------
        int idx = blk - 13824;            // 64 blocks: kcblk [0,8) x jblk [0,8)
        int kc = (idx >> 3) * 256;
        int j = (idx & 7) * 256 + tid;
        float (*se)[256] = (float(*)[256])sh;
        for (int i = tid; i < 2048; i += 256) {
            int bb = i >> 8, t = i & 255;
            float e = emb[bb * 2048 + kc + t];
            se[bb][t] = fast_silu(e);
        }
        __syncthreads();
        float acc[8] = {};
        #pragma unroll 4
        for (int t = 0; t < 256; t++) {
            float wv = Wemb[(size_t)(kc + t) * 2048 + j];
            #pragma unroll
            for (int bb = 0; bb < 8; bb++) acc[bb] += se[bb][t] * wv;
        }
        #pragma unroll
        for (int bb = 0; bb < 8; bb++)
            g_embp[((idx >> 3) * 8 + bb) * 2048 + j] = acc[bb];
    }
}

// ================= mma.sync bf16 GEMM body (4-stage cp.async, 1 sync/chunk) =================
static constexpr uint32_t TSTRIDE = 80;            // 32 bf16 + 8 pad bytes
static constexpr uint32_t TILE_B  = 128 * TSTRIDE; // 10240
static constexpr uint32_t STAGE_B = 2 * TILE_B;    // 20480 (A, B)
static constexpr int GEMM_SMEM = 4 * (int)STAGE_B; // 81920

// MODE: 1 = f32 out + residual, 2 = bf16 out
template<int MODE>
__device__ __forceinline__ void gemm_body(
    const __nv_bfloat16* __restrict__ A, const __nv_bfloat16* __restrict__ Bw,
    const float* __restrict__ bias, const float* __restrict__ R,
    float* __restrict__ Cf, __nv_bfloat16* __restrict__ Cb,
    int bm, int bn, int Nn, int K, uint32_t sbase) {
    int tid = threadIdx.x, wid = tid >> 5, lane = tid & 31;
    int wm = wid >> 2, wn = wid & 3;

    const __nv_bfloat16* gA = A  + (size_t)bm * K;
    const __nv_bfloat16* gB = Bw + (size_t)bn * K;

    float acc[4][4][4] = {};
    const int NC = K >> 5;

    auto load_stage = [&](int c) {
        uint32_t sb = sbase + (uint32_t)(c & 3) * STAGE_B;
        int kc = c * 32;
        #pragma unroll
        for (int i = tid; i < 512; i += 256) {
            int r = i >> 2, q = i & 3;
            CP_ASYNC16(sb + r * TSTRIDE + q * 16,          gA + (size_t)r * K + kc + q * 8);
            CP_ASYNC16(sb + TILE_B + r * TSTRIDE + q * 16, gB + (size_t)r * K + kc + q * 8);
        }
    };

    load_stage(0); CP_ASYNC_COMMIT();
    load_stage(1); CP_ASYNC_COMMIT();
    load_stage(2); CP_ASYNC_COMMIT();

    uint32_t aRow = (uint32_t)(wm * 64) + ((lane >> 3) & 1) * 8 + (lane & 7);
    uint32_t aCol = (lane >> 4) * 16;
    uint32_t bRow = (uint32_t)(wn * 32) + ((lane >> 4) * 8) + (lane & 7);
    uint32_t bCol = ((lane >> 3) & 1) * 16;

    for (int c = 0; c < NC; c++) {
        asm volatile("cp.async.wait_group 2;" ::: "memory");
        __syncthreads();
        if (c + 3 < NC) load_stage(c + 3);
        CP_ASYNC_COMMIT();

        uint32_t sb = sbase + (uint32_t)(c & 3) * STAGE_B;
        #pragma unroll
        for (int kk = 0; kk < 2; kk++) {
            uint32_t kOff = kk * 32;
            uint32_t ah[4][4], bh[4][2];
            #pragma unroll
            for (int mt = 0; mt < 4; mt++) {
                uint32_t ad = sb + (aRow + mt * 16) * TSTRIDE + aCol + kOff;
                ldsm_x4(ah[mt][0], ah[mt][1], ah[mt][2], ah[mt][3], ad);
            }
            #pragma unroll
            for (int np = 0; np < 2; np++) {
                uint32_t bd = sb + TILE_B + (bRow + np * 16) * TSTRIDE + bCol + kOff;
                ldsm_x4(bh[np*2][0], bh[np*2][1], bh[np*2+1][0], bh[np*2+1][1], bd);
            }
            #pragma unroll
            for (int mt = 0; mt < 4; mt++)
                #pragma unroll
                for (int nt = 0; nt < 4; nt++)
                    mma16816(acc[mt][nt], ah[mt], bh[nt]);
        }
    }

    int g = lane >> 2, tg = lane & 3;
    #pragma unroll
    for (int mt = 0; mt < 4; mt++) {
        int r0 = bm + wm * 64 + mt * 16 + g;
        #pragma unroll
        for (int nt = 0; nt < 4; nt++) {
            int col = bn + wn * 32 + nt * 8 + tg * 2;
            float b0 = bias[col], b1 = bias[col + 1];
            size_t o0 = (size_t)r0 * Nn + col;
            size_t o1 = (size_t)(r0 + 8) * Nn + col;
            float v00 = acc[mt][nt][0] + b0, v01 = acc[mt][nt][1] + b1;
            float v10 = acc[mt][nt][2] + b0, v11 = acc[mt][nt][3] + b1;
            if (MODE == 2) {
                *(uint32_t*)&Cb[o0] = pack_bf16x2(v00, v01);
                *(uint32_t*)&Cb[o1] = pack_bf16x2(v10, v11);
            } else {
                float2 r00 = *(const float2*)&R[o0];
                float2 r11 = *(const float2*)&R[o1];
                *(float2*)&Cf[o0] = make_float2(v00 + r00.x, v01 + r00.y);
                *(float2*)&Cf[o1] = make_float2(v10 + r11.x, v11 + r11.y);
            }
        }
    }
}

// ================= fused qkv GEMM + emb reduce + attention (R14) =================
// grid layout: [0,128) K tiles, [128,256) V tiles, [256,768) Q tiles,
//              [768,784) emb reduce, [784,1296) attention CTAs.
__global__ void __launch_bounds__(256, 2) qkv_attn_kernel(
    const float* __restrict__ bq, const float* __restrict__ bk, const float* __restrict__ bv,
    const float* __restrict__ bemb) {
    extern __shared__ char smem[];
    uint32_t sbase = smem_u32(smem);
    int tile = blockIdx.x;
    int tid = threadIdx.x;

    if (tile < 768) {
        // ---------------- projection GEMM tile ----------------
        const __nv_bfloat16 *A, *Bw; const float* bias; __nv_bfloat16* Cb; int K;
        int t;
        if (tile < 128)      { t = tile;       A = g_xfh; Bw = g_wk; bias = bk; Cb = g_kh; K = 768; }
        else if (tile < 256) { t = tile - 128; A = g_xfh; Bw = g_wv; bias = bv; Cb = g_vh; K = 768; }
        else                 { t = tile - 256; A = g_xnh; Bw = g_wq; bias = bq; Cb = g_qh; K = 1024; }
        int bm = (t >> 3) * 128, bn = (t & 7) * 128;
        gemm_body<2>(A, Bw, bias, nullptr, nullptr, Cb, bm, bn, 1024, K, sbase);
        __threadfence();
        __syncthreads();
        if (tid == 0) ((volatile int*)g_flags)[tile] = 1;
        return;
    }
    if (tile < 784) {
        // ---------------- emb reduce ----------------
        int base = (tile - 768) * 1024;
        for (int j4 = 0; j4 < 4; j4++) {
            int idx = base + tid + j4 * 256;
            int bb = idx >> 11, j = idx & 2047;
            float s = bemb[j];
            #pragma unroll
            for (int ky = 0; ky < 8; ky++) s += g_embp[(ky * 8 + bb) * 2048 + j];
            g_embo[bb * 2048 + j] = s;
        }
        return;
    }

    // ---------------- attention ----------------
    int a = tile - 784;
    int h = a & 15;
    int t2 = a >> 4;          // 0..31
    int b = t2 >> 2, qx = t2 & 3;
    int np = h >> 1;          // N-tile of this head

    if (tid < 6) {
        int grp = tid >> 1, i = tid & 1;
        int fid;
        if (grp == 0)      fid = (2 * b + i) * 8 + np;                 // K
        else if (grp == 1) fid = 128 + (2 * b + i) * 8 + np;           // V
        else               fid = 256 + (b * 8 + qx * 2 + i) * 8 + np;  // Q (both passes)
        while (((volatile int*)g_flags)[fid] == 0) {}
        __threadfence();
    }
    __syncthreads();

    __nv_bfloat16* Ks = (__nv_bfloat16*)smem;          // 256 x 72
    __nv_bfloat16* Vs = Ks + 256 * 72;
    uint32_t sbK = smem_u32(Ks), sbV = smem_u32(Vs);

    int w = tid >> 5, lane = tid & 31;
    int g = lane >> 2, t4 = lane & 3;
    const float SC = 0.125f * 1.44269504f;   // log2-domain scores

    for (int i = tid; i < 2048; i += 256) {
        int r = i >> 3, q8 = i & 7;
        size_t go = (size_t)(b * 256 + r) * 1024 + h * 64 + q8 * 8;
        *(uint4*)(Ks + r * 72 + q8 * 8) = *(const uint4*)(g_kh + go);
        *(uint4*)(Vs + r * 72 + q8 * 8) = *(const uint4*)(g_vh + go);
    }

    uint32_t aq[4][4];
    {
        int q0 = qx * 256;
        const __nv_bfloat16* qb = g_qh + (size_t)(b * 1024 + q0 + w * 16) * 1024 + h * 64;
        #pragma unroll
        for (int ks = 0; ks < 4; ks++) {
            aq[ks][0] = *(const uint32_t*)(qb + (size_t)g * 1024       + ks * 16 + 2 * t4);
            aq[ks][1] = *(const uint32_t*)(qb + (size_t)(g + 8) * 1024 + ks * 16 + 2 * t4);
            aq[ks][2] = *(const uint32_t*)(qb + (size_t)g * 1024       + ks * 16 + 8 + 2 * t4);
            aq[ks][3] = *(const uint32_t*)(qb + (size_t)(g + 8) * 1024 + ks * 16 + 8 + 2 * t4);
        }
    }
    __syncthreads();

    uint32_t bRowOff = ((lane >> 4) * 8 + (lane & 7));
    uint32_t bColOff = ((lane >> 3) & 1) * 16;
    uint32_t vRowOff = (((lane >> 3) & 1) * 8 + (lane & 7));
    uint32_t vColOff = (lane >> 4) * 16;

    for (int pass = 0; pass < 2; pass++) {
        int q0 = qx * 256 + pass * 128;
        if (pass == 1) {
            const __nv_bfloat16* qb = g_qh + (size_t)(b * 1024 + q0 + w * 16) * 1024 + h * 64;
            #pragma unroll
            for (int ks = 0; ks < 4; ks++) {
                aq[ks][0] = *(const uint32_t*)(qb + (size_t)g * 1024       + ks * 16 + 2 * t4);
                aq[ks][1] = *(const uint32_t*)(qb + (size_t)(g + 8) * 1024 + ks * 16 + 2 * t4);
                aq[ks][2] = *(const uint32_t*)(qb + (size_t)g * 1024       + ks * 16 + 8 + 2 * t4);
                aq[ks][3] = *(const uint32_t*)(qb + (size_t)(g + 8) * 1024 + ks * 16 + 8 + 2 * t4);
            }
        }

        float o[8][4] = {};
        float m0 = -1e30f, m1 = -1e30f, l0 = 0.f, l1 = 0.f;

        for (int c = 0; c < 4; c++) {
            int n0 = c * 64;
            float s[8][4] = {};
            #pragma unroll
            for (int ks = 0; ks < 4; ks++) {
                #pragma unroll
                for (int npp = 0; npp < 4; npp++) {
                    uint32_t r0, r1, r2, r3;
                    uint32_t bd = sbK + (n0 + npp * 16 + bRowOff) * 144 + bColOff + ks * 32;
                    ldsm_x4(r0, r1, r2, r3, bd);
                    uint32_t blo[2] = {r0, r1}, bhi[2] = {r2, r3};
                    mma16816(s[npp * 2],     aq[ks], blo);
                    mma16816(s[npp * 2 + 1], aq[ks], bhi);
                }
            }
            float mx0 = -1e30f, mx1 = -1e30f;
            #pragma unroll
            for (int j = 0; j < 8; j++) {
                #pragma unroll
                for (int r = 0; r < 4; r++) s[j][r] *= SC;
                mx0 = fmaxf(mx0, fmaxf(s[j][0], s[j][1]));
                mx1 = fmaxf(mx1, fmaxf(s[j][2], s[j][3]));
            }
            mx0 = fmaxf(mx0, __shfl_xor_sync(0xffffffffu, mx0, 1));
            mx0 = fmaxf(mx0, __shfl_xor_sync(0xffffffffu, mx0, 2));
            mx1 = fmaxf(mx1, __shfl_xor_sync(0xffffffffu, mx1, 1));
            mx1 = fmaxf(mx1, __shfl_xor_sync(0xffffffffu, mx1, 2));
            float nm0 = fmaxf(m0, mx0), nm1 = fmaxf(m1, mx1);
            float al0 = exp2f(m0 - nm0), al1 = exp2f(m1 - nm1);
            m0 = nm0; m1 = nm1;
            float sum0 = 0.f, sum1 = 0.f;
            #pragma unroll
            for (int j = 0; j < 8; j++) {
                s[j][0] = exp2f(s[j][0] - m0);
                s[j][1] = exp2f(s[j][1] - m0);
                s[j][2] = exp2f(s[j][2] - m1);
                s[j][3] = exp2f(s[j][3] - m1);
                sum0 += s[j][0] + s[j][1];
                sum1 += s[j][2] + s[j][3];
            }
            sum0 += __shfl_xor_sync(0xffffffffu, sum0, 1);
            sum0 += __shfl_xor_sync(0xffffffffu, sum0, 2);
            sum1 += __shfl_xor_sync(0xffffffffu, sum1, 1);
            sum1 += __shfl_xor_sync(0xffffffffu, sum1, 2);
            l0 = l0 * al0 + sum0;
            l1 = l1 * al1 + sum1;
            #pragma unroll
            for (int dt = 0; dt < 8; dt++) {
                o[dt][0] *= al0; o[dt][1] *= al0;
                o[dt][2] *= al1; o[dt][3] *= al1;
            }
            uint32_t pa[4][4];
            #pragma unroll
            for (int j = 0; j < 4; j++) {
                pa[j][0] = pack_bf16x2(s[2*j][0],   s[2*j][1]);
                pa[j][1] = pack_bf16x2(s[2*j][2],   s[2*j][3]);
                pa[j][2] = pack_bf16x2(s[2*j+1][0], s[2*j+1][1]);
                pa[j][3] = pack_bf16x2(s[2*j+1][2], s[2*j+1][3]);
            }
            #pragma unroll
            for (int j = 0; j < 4; j++) {
                #pragma unroll
                for (int dp = 0; dp < 4; dp++) {
                    uint32_t r0, r1, r2, r3;
                    uint32_t vd = sbV + (n0 + j * 16 + vRowOff) * 144 + dp * 32 + vColOff;
                    ldsm_x4_t(r0, r1, r2, r3, vd);
                    uint32_t blo[2] = {r0, r1}, bhi[2] = {r2, r3};
                    mma16816(o[dp * 2],     pa[j], blo);
                    mma16816(o[dp * 2 + 1], pa[j], bhi);
                }
            }
        }
        float inv0 = __frcp_rn(l0), inv1 = __frcp_rn(l1);
        __nv_bfloat16* yb = g_yh + (size_t)(b * 1024 + q0 + w * 16) * 1024 + h * 64;
        #pragma unroll
        for (int dt = 0; dt < 8; dt++) {
            int col = dt * 8 + 2 * t4;
            *(uint32_t*)(yb + (size_t)g * 1024 + col)       = pack_bf16x2(o[dt][0] * inv0, o[dt][1] * inv0);
            *(uint32_t*)(yb + (size_t)(g + 8) * 1024 + col) = pack_bf16x2(o[dt][2] * inv1, o[dt][3] * inv1);
        }
    }
}

// ================= fused modulate + out-projection =================
// grid: [0,1024) modulate groups (8 rows, warp-per-row), [1024,1536) outproj tiles.
__global__ void __launch_bounds__(256, 2) mod_outproj_kernel(
    const float* __restrict__ sln_g, const float* __restrict__ sln_b,
    const float* __restrict__ bout, const float* __restrict__ x, float* __restrict__ out) {
    extern __shared__ char smem[];
    uint32_t sbase = smem_u32(smem);
    int tile = blockIdx.x;
    int tid = threadIdx.x;

    if (tile < 1024) {
        // ---------- modulate: 8 rows, one warp per row, no block syncs ----------
        int w = tid >> 5, lane = tid & 31;
        int row = tile * 8 + w;
        int b = row >> 10;
        const __nv_bfloat16* yr = g_yh + (size_t)row * 1024;
        const float* embS = g_embo + b * 2048;
        float vals[32];
        float sum = 0.f, sq = 0.f;
        #pragma unroll
        for (int j = 0; j < 8; j++) {
            uint2 y2 = *(const uint2*)(yr + lane * 4 + j * 128);
            __nv_bfloat162 p0 = *(__nv_bfloat162*)&y2.x;
            __nv_bfloat162 p1 = *(__nv_bfloat162*)&y2.y;
            float a0 = __bfloat162float(p0.x), a1 = __bfloat162float(p0.y);
            float a2 = __bfloat162float(p1.x), a3 = __bfloat162float(p1.y);
            vals[j*4+0] = a0; vals[j*4+1] = a1; vals[j*4+2] = a2; vals[j*4+3] = a3;
            sum += a0 + a1 + a2 + a3;
            sq  += a0*a0 + a1*a1 + a2*a2 + a3*a3;
        }
        #pragma unroll
        for (int o = 16; o; o >>= 1) {
            sum += __shfl_xor_sync(0xffffffffu, sum, o);
            sq  += __shfl_xor_sync(0xffffffffu, sq,  o);
        }
        float mean = sum * (1.f / 1024.f);
        float inv = rsqrtf(sq * (1.f / 1024.f) - mean * mean + 1e-5f);
        #pragma unroll
        for (int j = 0; j < 8; j++) {
            int i0 = lane * 4 + j * 128;
            float4 gg = *(const float4*)(sln_g + i0);
            float4 bb = *(const float4*)(sln_b + i0);
            float4 sc = *(const float4*)(embS + i0);
            float4 sf = *(const float4*)(embS + 1024 + i0);
            float h0 = fast_silu(((vals[j*4+0] - mean) * inv * gg.x + bb.x) * (1.f + sc.x) + sf.x);
            float h1 = fast_silu(((vals[j*4+1] - mean) * inv * gg.y + bb.y) * (1.f + sc.y) + sf.y);
            float h2 = fast_silu(((vals[j*4+2] - mean) * inv * gg.z + bb.z) * (1.f + sc.z) + sf.z);
            float h3 = fast_silu(((vals[j*4+3] - mean) * inv * gg.w + bb.w) * (1.f + sc.w) + sf.w);
            uint2 o2;
            o2.x = pack_bf16x2(h0, h1);
            o2.y = pack_bf16x2(h2, h3);
            *(uint2*)(g_hnh + (size_t)row * 1024 + i0) = o2;
        }
        __threadfence();
        __syncthreads();
        if (tid == 0) ((volatile int*)g_mod_flag)[tile] = 1;
        return;
    }

    // ---------- out-projection tile ----------
    int t = tile - 1024;                 // 0..511
    int bm = (t >> 3) * 128, bn = (t & 7) * 128;
    if (tid < 16) {
        int gid = (bm >> 3) + tid;       // 16 groups of 8 rows covering [bm, bm+128)
        while (((volatile int*)g_mod_flag)[gid] == 0) {}
        __threadfence();
    }
    __syncthreads();
    gemm_body<1>(g_hnh, g_wo, bout, x, out, nullptr, bm, bn, 1024, 1024, sbase);
}

// ================= launch =================
extern "C" void kernel_launch(void* const* d_in, const int* in_sizes, int n_in,
                              void* d_out, int out_size) {
    const float* x     = (const float*)d_in[0];
    const float* xf    = (const float*)d_in[1];
    const float* emb   = (const float*)d_in[2];
    const float* ln_g  = (const float*)d_in[3];
    const float* ln_b  = (const float*)d_in[4];
    const float* cln_g = (const float*)d_in[5];
    const float* cln_b = (const float*)d_in[6];
    const float* Wq    = (const float*)d_in[7];
    const float* bq    = (const float*)d_in[8];
    const float* Wk    = (const float*)d_in[9];
    const float* bk    = (const float*)d_in[10];
    const float* Wv    = (const float*)d_in[11];
    const float* bv    = (const float*)d_in[12];
    const float* sln_g = (const float*)d_in[13];
    const float* sln_b = (const float*)d_in[14];
    const float* Wemb  = (const float*)d_in[15];
    const float* bemb  = (const float*)d_in[16];
    const float* Wout  = (const float*)d_in[17];
    const float* bout  = (const float*)d_in[18];
    float* out = (float*)d_out;

    cudaFuncSetAttribute(qkv_attn_kernel,    cudaFuncAttributeMaxDynamicSharedMemorySize, GEMM_SMEM);
    cudaFuncSetAttribute(mod_outproj_kernel, cudaFuncAttributeMaxDynamicSharedMemorySize, GEMM_SMEM);

    // 1) preprocess: LN(x), LN(xf), weight transposes, emb split-K partials, flag reset
    preprocess_kernel<<<13888, 256>>>(x, ln_g, ln_b, xf, cln_g, cln_b,
                                      Wq, Wk, Wv, Wout, emb, Wemb);

    // 2) fused q/k/v projections + emb reduce + attention (producer-consumer flags)
    qkv_attn_kernel<<<1296, 256, GEMM_SMEM>>>(bq, bk, bv, bemb);

    // 3) fused modulate + output projection (+ residual)
    mod_outproj_kernel<<<1536, 256, GEMM_SMEM>>>(sln_g, sln_b, bout, x, out);
}

// round 17
// speedup vs baseline: 1.4936x; 1.4936x over previous
#include <cuda_runtime.h>
#include <cuda_bf16.h>
#include <cstdint>
#include <cstddef>

// Problem constants: B=8, T=1024, D=1024, N=256, L=768, H=16, hd=64, TE=2048

// ================= helpers =================
__device__ __forceinline__ uint32_t smem_u32(const void* p) {
    uint32_t a;
    asm("{ .reg .u64 t; cvta.to.shared.u64 t, %1; cvt.u32.u64 %0, t; }" : "=r"(a) : "l"(p));
    return a;
}
#define CP_ASYNC16(smem, gptr) \
    asm volatile("cp.async.cg.shared.global [%0], [%1], 16;" :: "r"(smem), "l"(gptr))
#define CP_ASYNC_COMMIT() asm volatile("cp.async.commit_group;" ::: "memory")

__device__ __forceinline__ void ldsm_x4(uint32_t& r0, uint32_t& r1, uint32_t& r2, uint32_t& r3,
                                        uint32_t addr) {
    asm volatile("ldmatrix.sync.aligned.m8n8.x4.shared.b16 {%0,%1,%2,%3}, [%4];"
                 : "=r"(r0), "=r"(r1), "=r"(r2), "=r"(r3) : "r"(addr));
}
__device__ __forceinline__ void ldsm_x4_t(uint32_t& r0, uint32_t& r1, uint32_t& r2, uint32_t& r3,
                                          uint32_t addr) {
    asm volatile("ldmatrix.sync.aligned.m8n8.x4.trans.shared.b16 {%0,%1,%2,%3}, [%4];"
                 : "=r"(r0), "=r"(r1), "=r"(r2), "=r"(r3) : "r"(addr));
}
__device__ __forceinline__ void mma16816(float* d, const uint32_t* a, const uint32_t* b) {
    asm volatile("mma.sync.aligned.m16n8k16.row.col.f32.bf16.bf16.f32 "
                 "{%0,%1,%2,%3}, {%4,%5,%6,%7}, {%8,%9}, {%0,%1,%2,%3};"
                 : "+f"(d[0]), "+f"(d[1]), "+f"(d[2]), "+f"(d[3])
                 : "r"(a[0]), "r"(a[1]), "r"(a[2]), "r"(a[3]), "r"(b[0]), "r"(b[1]));
}
__device__ __forceinline__ uint32_t pack_bf16x2(float a, float b) {
    __nv_bfloat162 h = __floats2bfloat162_rn(a, b);
    return *(uint32_t*)&h;
}
__device__ __forceinline__ float fast_silu(float h) {
    return __fdividef(h, 1.f + __expf(-h));
}

// ================= scratch (device globals) =================
__device__ float g_embo[8u*2048u];
__device__ float g_embp[8u*8u*2048u];          // split-K partials [ky][b][j]
__device__ int   g_flags[768];                 // per-gemm-tile completion flags
__device__ __nv_bfloat16 g_yh [8192u*1024u];   // attn out bf16
__device__ __nv_bfloat16 g_xnh[8192u*1024u];   // LN(x) bf16
__device__ __nv_bfloat16 g_xfh[2048u*768u];    // LN(xf) bf16
__device__ __nv_bfloat16 g_qh [8192u*1024u];
__device__ __nv_bfloat16 g_kh [2048u*1024u];
__device__ __nv_bfloat16 g_vh [2048u*1024u];
__device__ __nv_bfloat16 g_hnh[8192u*1024u];
__device__ __nv_bfloat16 g_wq [1024u*1024u];   // W^T bf16 [N,K]
__device__ __nv_bfloat16 g_wk [1024u*768u];
__device__ __nv_bfloat16 g_wv [1024u*768u];
__device__ __nv_bfloat16 g_wo [1024u*768u + 1024u*256u]; // (1024*1024)

// ---- warp-per-row LayerNorm: NF4 float4 per lane (8 for D=1024, 6 for L=768) ----
template<int NF4>
__device__ __forceinline__ void ln_warp_row(const float* __restrict__ xr,
                                            const float* __restrict__ gam,
                                            const float* __restrict__ bet,
                                            __nv_bfloat16* __restrict__ orow, int lane) {
    float4 v[NF4];
    float sum = 0.f, sq = 0.f;
    #pragma unroll
    for (int j = 0; j < NF4; j++) {
        v[j] = *(const float4*)(xr + lane * 4 + j * 128);
        sum += v[j].x + v[j].y + v[j].z + v[j].w;
        sq  += v[j].x * v[j].x + v[j].y * v[j].y + v[j].z * v[j].z + v[j].w * v[j].w;
    }
    #pragma unroll
    for (int o = 16; o; o >>= 1) {
        sum += __shfl_xor_sync(0xffffffffu, sum, o);
        sq  += __shfl_xor_sync(0xffffffffu, sq,  o);
    }
    const float Wd = NF4 * 128.f;
    float mean = sum / Wd;
    float inv = rsqrtf(sq / Wd - mean * mean + 1e-5f);
    #pragma unroll
    for (int j = 0; j < NF4; j++) {
        int i0 = lane * 4 + j * 128;
        float4 gg = *(const float4*)(gam + i0);
        float4 bb = *(const float4*)(bet + i0);
        uint2 o2;
        o2.x = pack_bf16x2((v[j].x - mean) * inv * gg.x + bb.x,
                           (v[j].y - mean) * inv * gg.y + bb.y);
        o2.y = pack_bf16x2((v[j].z - mean) * inv * gg.z + bb.z,
                           (v[j].w - mean) * inv * gg.w + bb.w);
        *(uint2*)(orow + i0) = o2;
    }
}

// ================= fused preprocess: LN (warp-per-row), 4x weight transpose, emb split-K =================
// grid: [0,1024) x-LN (8 rows/blk), [1024,1280) xf-LN (8 rows/blk),
//       [1280,4864) wsplit tiles, [4864,4928) emb split-K blocks. 256 thr.
__global__ void __launch_bounds__(256) preprocess_kernel(
    const float* __restrict__ x,  const float* __restrict__ ln_g, const float* __restrict__ ln_b,
    const float* __restrict__ xf, const float* __restrict__ cg,   const float* __restrict__ cb,
    const float* __restrict__ Wq, const float* __restrict__ Wk,
    const float* __restrict__ Wv, const float* __restrict__ Wo,
    const float* __restrict__ emb, const float* __restrict__ Wemb) {
    __shared__ float sh[2112];
    int blk = blockIdx.x;
    int tid = threadIdx.x;

    if (blk == 0) {
        for (int i = tid; i < 768; i += 256) g_flags[i] = 0;
    }

    if (blk < 1024) {
        // ---------- LN(x): 8 rows, one warp per row ----------
        int w = tid >> 5, lane = tid & 31;
        int row = blk * 8 + w;
        ln_warp_row<8>(x + (size_t)row * 1024, ln_g, ln_b, g_xnh + (size_t)row * 1024, lane);
    } else if (blk < 1280) {
        // ---------- LN(xf): 8 rows, one warp per row ----------
        int w = tid >> 5, lane = tid & 31;
        int row = (blk - 1024) * 8 + w;
        ln_warp_row<6>(xf + (size_t)row * 768, cg, cb, g_xfh + (size_t)row * 768, lane);
    } else if (blk < 4864) {
        // ---------- weight transpose W[K,N] -> T[N,K] bf16 ----------
        int idx = blk - 1280;
        const float* W; __nv_bfloat16* Th; int K, kt;
        if (idx < 1024)      { W = Wq; Th = g_wq; K = 1024; kt = 32; }
        else if (idx < 1792) { W = Wk; Th = g_wk; K = 768;  kt = 24; idx -= 1024; }
        else if (idx < 2560) { W = Wv; Th = g_wv; K = 768;  kt = 24; idx -= 1792; }
        else                 { W = Wo; Th = g_wo; K = 1024; kt = 32; idx -= 2560; }
        int k0 = (idx % kt) * 32, n0 = (idx / kt) * 32;
        float (*t)[33] = (float(*)[33])sh;
        int tx = tid & 31, ty = tid >> 5;
        #pragma unroll
        for (int r = ty; r < 32; r += 8)
            t[r][tx] = W[(size_t)(k0 + r) * 1024 + n0 + tx];
        __syncthreads();
        #pragma unroll
        for (int r = ty; r < 32; r += 8)
            Th[(size_t)(n0 + r) * K + k0 + tx] = __float2bfloat16(t[tx][r]);
    } else {
        // ---------- silu(emb) @ Wemb split-K partials ----------
        int idx = blk - 4864;             // 64 blocks: kcblk [0,8) x jblk [0,8)
        int kc = (idx >> 3) * 256;
        int j = (idx & 7) * 256 + tid;
        float (*se)[256] = (float(*)[256])sh;
        for (int i = tid; i < 2048; i += 256) {
            int bb = i >> 8, t = i & 255;
            float e = emb[bb * 2048 + kc + t];
            se[bb][t] = fast_silu(e);
        }
        __syncthreads();
        float acc[8] = {};
        #pragma unroll 4
        for (int t = 0; t < 256; t++) {
            float wv = Wemb[(size_t)(kc + t) * 2048 + j];
            #pragma unroll
            for (int bb = 0; bb < 8; bb++) acc[bb] += se[bb][t] * wv;
        }
        #pragma unroll
        for (int bb = 0; bb < 8; bb++)
            g_embp[((idx >> 3) * 8 + bb) * 2048 + j] = acc[bb];
    }
}

// ================= mma.sync bf16 GEMM body (4-stage cp.async, 1 sync/chunk) =================
static constexpr uint32_t TSTRIDE = 80;            // 32 bf16 + 8 pad bytes
static constexpr uint32_t TILE_B  = 128 * TSTRIDE; // 10240
static constexpr uint32_t STAGE_B = 2 * TILE_B;    // 20480 (A, B)
static constexpr int GEMM_SMEM = 4 * (int)STAGE_B; // 81920

// MODE: 1 = f32 out + residual, 2 = bf16 out
template<int MODE>
__device__ __forceinline__ void gemm_body(
    const __nv_bfloat16* __restrict__ A, const __nv_bfloat16* __restrict__ Bw,
    const float* __restrict__ bias, const float* __restrict__ R,
    float* __restrict__ Cf, __nv_bfloat16* __restrict__ Cb,
    int bm, int bn, int Nn, int K, uint32_t sbase) {
    int tid = threadIdx.x, wid = tid >> 5, lane = tid & 31;
    int wm = wid >> 2, wn = wid & 3;

    const __nv_bfloat16* gA = A  + (size_t)bm * K;
    const __nv_bfloat16* gB = Bw + (size_t)bn * K;

    float acc[4][4][4] = {};
    const int NC = K >> 5;

    auto load_stage = [&](int c) {
        uint32_t sb = sbase + (uint32_t)(c & 3) * STAGE_B;
        int kc = c * 32;
        #pragma unroll
        for (int i = tid; i < 512; i += 256) {
            int r = i >> 2, q = i & 3;
            CP_ASYNC16(sb + r * TSTRIDE + q * 16,          gA + (size_t)r * K + kc + q * 8);
            CP_ASYNC16(sb + TILE_B + r * TSTRIDE + q * 16, gB + (size_t)r * K + kc + q * 8);
        }
    };

    load_stage(0); CP_ASYNC_COMMIT();
    load_stage(1); CP_ASYNC_COMMIT();
    load_stage(2); CP_ASYNC_COMMIT();

    uint32_t aRow = (uint32_t)(wm * 64) + ((lane >> 3) & 1) * 8 + (lane & 7);
    uint32_t aCol = (lane >> 4) * 16;
    uint32_t bRow = (uint32_t)(wn * 32) + ((lane >> 4) * 8) + (lane & 7);
    uint32_t bCol = ((lane >> 3) & 1) * 16;

    for (int c = 0; c < NC; c++) {
        asm volatile("cp.async.wait_group 2;" ::: "memory");
        __syncthreads();
        if (c + 3 < NC) load_stage(c + 3);
        CP_ASYNC_COMMIT();

        uint32_t sb = sbase + (uint32_t)(c & 3) * STAGE_B;
        #pragma unroll
        for (int kk = 0; kk < 2; kk++) {
            uint32_t kOff = kk * 32;
            uint32_t ah[4][4], bh[4][2];
            #pragma unroll
            for (int mt = 0; mt < 4; mt++) {
                uint32_t ad = sb + (aRow + mt * 16) * TSTRIDE + aCol + kOff;
                ldsm_x4(ah[mt][0], ah[mt][1], ah[mt][2], ah[mt][3], ad);
            }
            #pragma unroll
            for (int np = 0; np < 2; np++) {
                uint32_t bd = sb + TILE_B + (bRow + np * 16) * TSTRIDE + bCol + kOff;
                ldsm_x4(bh[np*2][0], bh[np*2][1], bh[np*2+1][0], bh[np*2+1][1], bd);
            }
            #pragma unroll
            for (int mt = 0; mt < 4; mt++)
                #pragma unroll
                for (int nt = 0; nt < 4; nt++)
                    mma16816(acc[mt][nt], ah[mt], bh[nt]);
        }
    }

    int g = lane >> 2, tg = lane & 3;
    #pragma unroll
    for (int mt = 0; mt < 4; mt++) {
        int r0 = bm + wm * 64 + mt * 16 + g;
        #pragma unroll
        for (int nt = 0; nt < 4; nt++) {
            int col = bn + wn * 32 + nt * 8 + tg * 2;
            float b0 = bias[col], b1 = bias[col + 1];
            size_t o0 = (size_t)r0 * Nn + col;
            size_t o1 = (size_t)(r0 + 8) * Nn + col;
            float v00 = acc[mt][nt][0] + b0, v01 = acc[mt][nt][1] + b1;
            float v10 = acc[mt][nt][2] + b0, v11 = acc[mt][nt][3] + b1;
            if (MODE == 2) {
                *(uint32_t*)&Cb[o0] = pack_bf16x2(v00, v01);
                *(uint32_t*)&Cb[o1] = pack_bf16x2(v10, v11);
            } else {
                float2 r00 = *(const float2*)&R[o0];
                float2 r11 = *(const float2*)&R[o1];
                *(float2*)&Cf[o0] = make_float2(v00 + r00.x, v01 + r00.y);
                *(float2*)&Cf[o1] = make_float2(v10 + r11.x, v11 + r11.y);
            }
        }
    }
}

// ================= fused qkv GEMM + emb reduce + attention (R14) =================
// grid layout: [0,128) K tiles, [128,256) V tiles, [256,768) Q tiles,
//              [768,784) emb reduce, [784,1296) attention CTAs.
__global__ void __launch_bounds__(256, 2) qkv_attn_kernel(
    const float* __restrict__ bq, const float* __restrict__ bk, const float* __restrict__ bv,
    const float* __restrict__ bemb) {
    extern __shared__ char smem[];
    uint32_t sbase = smem_u32(smem);
    int tile = blockIdx.x;
    int tid = threadIdx.x;

    if (tile < 768) {
        const __nv_bfloat16 *A, *Bw; const float* bias; __nv_bfloat16* Cb; int K;
        int t;
        if (tile < 128)      { t = tile;       A = g_xfh; Bw = g_wk; bias = bk; Cb = g_kh; K = 768; }
        else if (tile < 256) { t = tile - 128; A = g_xfh; Bw = g_wv; bias = bv; Cb = g_vh; K = 768; }
        else                 { t = tile - 256; A = g_xnh; Bw = g_wq; bias = bq; Cb = g_qh; K = 1024; }
        int bm = (t >> 3) * 128, bn = (t & 7) * 128;
        gemm_body<2>(A, Bw, bias, nullptr, nullptr, Cb, bm, bn, 1024, K, sbase);
        __threadfence();
        __syncthreads();
        if (tid == 0) ((volatile int*)g_flags)[tile] = 1;
        return;
    }
    if (tile < 784) {
        int base = (tile - 768) * 1024;
        for (int j4 = 0; j4 < 4; j4++) {
            int idx = base + tid + j4 * 256;
            int bb = idx >> 11, j = idx & 2047;
            float s = bemb[j];
            #pragma unroll
            for (int ky = 0; ky < 8; ky++) s += g_embp[(ky * 8 + bb) * 2048 + j];
            g_embo[bb * 2048 + j] = s;
        }
        return;
    }

    // ---------------- attention ----------------
    int a = tile - 784;
    int h = a & 15;
    int t2 = a >> 4;
    int b = t2 >> 2, qx = t2 & 3;
    int np = h >> 1;

    if (tid < 6) {
        int grp = tid >> 1, i = tid & 1;
        int fid;
        if (grp == 0)      fid = (2 * b + i) * 8 + np;
        else if (grp == 1) fid = 128 + (2 * b + i) * 8 + np;
        else               fid = 256 + (b * 8 + qx * 2 + i) * 8 + np;
        while (((volatile int*)g_flags)[fid] == 0) {}
        __threadfence();
    }
    __syncthreads();

    __nv_bfloat16* Ks = (__nv_bfloat16*)smem;          // 256 x 72
    __nv_bfloat16* Vs = Ks + 256 * 72;
    uint32_t sbK = smem_u32(Ks), sbV = smem_u32(Vs);

    int w = tid >> 5, lane = tid & 31;
    int g = lane >> 2, t4 = lane & 3;
    const float SC = 0.125f * 1.44269504f;

    for (int i = tid; i < 2048; i += 256) {
        int r = i >> 3, q8 = i & 7;
        size_t go = (size_t)(b * 256 + r) * 1024 + h * 64 + q8 * 8;
        *(uint4*)(Ks + r * 72 + q8 * 8) = *(const uint4*)(g_kh + go);
        *(uint4*)(Vs + r * 72 + q8 * 8) = *(const uint4*)(g_vh + go);
    }

    uint32_t aq[4][4];
    {
        int q0 = qx * 256;
        const __nv_bfloat16* qb = g_qh + (size_t)(b * 1024 + q0 + w * 16) * 1024 + h * 64;
        #pragma unroll
        for (int ks = 0; ks < 4; ks++) {
            aq[ks][0] = *(const uint32_t*)(qb + (size_t)g * 1024       + ks * 16 + 2 * t4);
            aq[ks][1] = *(const uint32_t*)(qb + (size_t)(g + 8) * 1024 + ks * 16 + 2 * t4);
            aq[ks][2] = *(const uint32_t*)(qb + (size_t)g * 1024       + ks * 16 + 8 + 2 * t4);
            aq[ks][3] = *(const uint32_t*)(qb + (size_t)(g + 8) * 1024 + ks * 16 + 8 + 2 * t4);
        }
    }
    __syncthreads();

    uint32_t bRowOff = ((lane >> 4) * 8 + (lane & 7));
    uint32_t bColOff = ((lane >> 3) & 1) * 16;
    uint32_t vRowOff = (((lane >> 3) & 1) * 8 + (lane & 7));
    uint32_t vColOff = (lane >> 4) * 16;

    for (int pass = 0; pass < 2; pass++) {
        int q0 = qx * 256 + pass * 128;
        if (pass == 1) {
            const __nv_bfloat16* qb = g_qh + (size_t)(b * 1024 + q0 + w * 16) * 1024 + h * 64;
            #pragma unroll
            for (int ks = 0; ks < 4; ks++) {
                aq[ks][0] = *(const uint32_t*)(qb + (size_t)g * 1024       + ks * 16 + 2 * t4);
                aq[ks][1] = *(const uint32_t*)(qb + (size_t)(g + 8) * 1024 + ks * 16 + 2 * t4);
                aq[ks][2] = *(const uint32_t*)(qb + (size_t)g * 1024       + ks * 16 + 8 + 2 * t4);
                aq[ks][3] = *(const uint32_t*)(qb + (size_t)(g + 8) * 1024 + ks * 16 + 8 + 2 * t4);
            }
        }

        float o[8][4] = {};
        float m0 = -1e30f, m1 = -1e30f, l0 = 0.f, l1 = 0.f;

        for (int c = 0; c < 4; c++) {
            int n0 = c * 64;
            float s[8][4] = {};
            #pragma unroll
            for (int ks = 0; ks < 4; ks++) {
                #pragma unroll
                for (int npp = 0; npp < 4; npp++) {
                    uint32_t r0, r1, r2, r3;
                    uint32_t bd = sbK + (n0 + npp * 16 + bRowOff) * 144 + bColOff + ks * 32;
                    ldsm_x4(r0, r1, r2, r3, bd);
                    uint32_t blo[2] = {r0, r1}, bhi[2] = {r2, r3};
                    mma16816(s[npp * 2],     aq[ks], blo);
                    mma16816(s[npp * 2 + 1], aq[ks], bhi);
                }
            }
            float mx0 = -1e30f, mx1 = -1e30f;
            #pragma unroll
            for (int j = 0; j < 8; j++) {
                #pragma unroll
                for (int r = 0; r < 4; r++) s[j][r] *= SC;
                mx0 = fmaxf(mx0, fmaxf(s[j][0], s[j][1]));
                mx1 = fmaxf(mx1, fmaxf(s[j][2], s[j][3]));
            }
            mx0 = fmaxf(mx0, __shfl_xor_sync(0xffffffffu, mx0, 1));
            mx0 = fmaxf(mx0, __shfl_xor_sync(0xffffffffu, mx0, 2));
            mx1 = fmaxf(mx1, __shfl_xor_sync(0xffffffffu, mx1, 1));
            mx1 = fmaxf(mx1, __shfl_xor_sync(0xffffffffu, mx1, 2));
            float nm0 = fmaxf(m0, mx0), nm1 = fmaxf(m1, mx1);
            float al0 = exp2f(m0 - nm0), al1 = exp2f(m1 - nm1);
            m0 = nm0; m1 = nm1;
            float sum0 = 0.f, sum1 = 0.f;
            #pragma unroll
            for (int j = 0; j < 8; j++) {
                s[j][0] = exp2f(s[j][0] - m0);
                s[j][1] = exp2f(s[j][1] - m0);
                s[j][2] = exp2f(s[j][2] - m1);
                s[j][3] = exp2f(s[j][3] - m1);
                sum0 += s[j][0] + s[j][1];
                sum1 += s[j][2] + s[j][3];
            }
            sum0 += __shfl_xor_sync(0xffffffffu, sum0, 1);
            sum0 += __shfl_xor_sync(0xffffffffu, sum0, 2);
            sum1 += __shfl_xor_sync(0xffffffffu, sum1, 1);
            sum1 += __shfl_xor_sync(0xffffffffu, sum1, 2);
            l0 = l0 * al0 + sum0;
            l1 = l1 * al1 + sum1;
            #pragma unroll
            for (int dt = 0; dt < 8; dt++) {
                o[dt][0] *= al0; o[dt][1] *= al0;
                o[dt][2] *= al1; o[dt][3] *= al1;
            }
            uint32_t pa[4][4];
            #pragma unroll
            for (int j = 0; j < 4; j++) {
                pa[j][0] = pack_bf16x2(s[2*j][0],   s[2*j][1]);
                pa[j][1] = pack_bf16x2(s[2*j][2],   s[2*j][3]);
                pa[j][2] = pack_bf16x2(s[2*j+1][0], s[2*j+1][1]);
                pa[j][3] = pack_bf16x2(s[2*j+1][2], s[2*j+1][3]);
            }
            #pragma unroll
            for (int j = 0; j < 4; j++) {
                #pragma unroll
                for (int dp = 0; dp < 4; dp++) {
                    uint32_t r0, r1, r2, r3;
                    uint32_t vd = sbV + (n0 + j * 16 + vRowOff) * 144 + dp * 32 + vColOff;
                    ldsm_x4_t(r0, r1, r2, r3, vd);
                    uint32_t blo[2] = {r0, r1}, bhi[2] = {r2, r3};
                    mma16816(o[dp * 2],     pa[j], blo);
                    mma16816(o[dp * 2 + 1], pa[j], bhi);
                }
            }
        }
        float inv0 = __frcp_rn(l0), inv1 = __frcp_rn(l1);
        __nv_bfloat16* yb = g_yh + (size_t)(b * 1024 + q0 + w * 16) * 1024 + h * 64;
        #pragma unroll
        for (int dt = 0; dt < 8; dt++) {
            int col = dt * 8 + 2 * t4;
            *(uint32_t*)(yb + (size_t)g * 1024 + col)       = pack_bf16x2(o[dt][0] * inv0, o[dt][1] * inv0);
            *(uint32_t*)(yb + (size_t)(g + 8) * 1024 + col) = pack_bf16x2(o[dt][2] * inv1, o[dt][3] * inv1);
        }
    }
}

// ================= LN(y)*(1+scale)+shift -> silu -> bf16 (vectorized, fast-div) =================
__global__ void __launch_bounds__(256) modulate_kernel(const float* __restrict__ gam,
                                                       const float* __restrict__ bet) {
    int row = blockIdx.x;
    int b = row >> 10;
    const __nv_bfloat16* yr = g_yh + (size_t)row * 1024;
    int i0 = threadIdx.x * 4;
    uint2 y2 = *(const uint2*)(yr + i0);
    __nv_bfloat162 p0 = *(__nv_bfloat162*)&y2.x;
    __nv_bfloat162 p1 = *(__nv_bfloat162*)&y2.y;
    float v0 = __bfloat162float(p0.x), v1 = __bfloat162float(p0.y);
    float v2 = __bfloat162float(p1.x), v3 = __bfloat162float(p1.y);
    float sum = v0 + v1 + v2 + v3;
    float sq  = v0 * v0 + v1 * v1 + v2 * v2 + v3 * v3;
    __shared__ float s1[8], s2[8];
    #pragma unroll
    for (int o = 16; o; o >>= 1) {
        sum += __shfl_xor_sync(0xffffffffu, sum, o);
        sq  += __shfl_xor_sync(0xffffffffu, sq,  o);
    }
    int w = threadIdx.x >> 5, l = threadIdx.x & 31;
    if (l == 0) { s1[w] = sum; s2[w] = sq; }
    __syncthreads();
    __shared__ float mean_s, inv_s;
    if (threadIdx.x == 0) {
        float ts = 0.f, tq = 0.f;
        for (int i = 0; i < 8; i++) { ts += s1[i]; tq += s2[i]; }
        float mean = ts * (1.f / 1024.f);
        float var = tq * (1.f / 1024.f) - mean * mean;
        mean_s = mean;
        inv_s = rsqrtf(var + 1e-5f);
    }
    __syncthreads();
    float mean = mean_s, inv = inv_s;
    float4 gg = *(const float4*)(gam + i0);
    float4 bb = *(const float4*)(bet + i0);
    float4 sc = *(const float4*)(g_embo + b * 2048 + i0);
    float4 shf = *(const float4*)(g_embo + b * 2048 + 1024 + i0);
    float n0 = (v0 - mean) * inv * gg.x + bb.x;
    float n1 = (v1 - mean) * inv * gg.y + bb.y;
    float n2 = (v2 - mean) * inv * gg.z + bb.z;
    float n3 = (v3 - mean) * inv * gg.w + bb.w;
    float h0 = fast_silu(n0 * (1.f + sc.x) + shf.x);
    float h1 = fast_silu(n1 * (1.f + sc.y) + shf.y);
    float h2 = fast_silu(n2 * (1.f + sc.z) + shf.z);
    float h3 = fast_silu(n3 * (1.f + sc.w) + shf.w);
    uint2 o2;
    o2.x = pack_bf16x2(h0, h1);
    o2.y = pack_bf16x2(h2, h3);
    *(uint2*)(g_hnh + (size_t)row * 1024 + i0) = o2;
}

// out-projection GEMM + residual
__global__ void __launch_bounds__(256) outproj_gemm_kernel(
    const float* __restrict__ bout, const float* __restrict__ x, float* __restrict__ out) {
    extern __shared__ char smem[];
    uint32_t sbase = smem_u32(smem);
    gemm_body<1>(g_hnh, g_wo, bout, x, out, nullptr, blockIdx.y * 128, blockIdx.x * 128,
                 1024, 1024, sbase);
}

// ================= launch =================
extern "C" void kernel_launch(void* const* d_in, const int* in_sizes, int n_in,
                              void* d_out, int out_size) {
    const float* x     = (const float*)d_in[0];
    const float* xf    = (const float*)d_in[1];
    const float* emb   = (const float*)d_in[2];
    const float* ln_g  = (const float*)d_in[3];
    const float* ln_b  = (const float*)d_in[4];
    const float* cln_g = (const float*)d_in[5];
    const float* cln_b = (const float*)d_in[6];
    const float* Wq    = (const float*)d_in[7];
    const float* bq    = (const float*)d_in[8];
    const float* Wk    = (const float*)d_in[9];
    const float* bk    = (const float*)d_in[10];
    const float* Wv    = (const float*)d_in[11];
    const float* bv    = (const float*)d_in[12];
    const float* sln_g = (const float*)d_in[13];
    const float* sln_b = (const float*)d_in[14];
    const float* Wemb  = (const float*)d_in[15];
    const float* bemb  = (const float*)d_in[16];
    const float* Wout  = (const float*)d_in[17];
    const float* bout  = (const float*)d_in[18];
    float* out = (float*)d_out;

    cudaFuncSetAttribute(qkv_attn_kernel,     cudaFuncAttributeMaxDynamicSharedMemorySize, GEMM_SMEM);
    cudaFuncSetAttribute(outproj_gemm_kernel, cudaFuncAttributeMaxDynamicSharedMemorySize, GEMM_SMEM);

    // 1) preprocess: warp-per-row LNs, weight transposes, emb split-K partials, flag reset
    preprocess_kernel<<<4928, 256>>>(x, ln_g, ln_b, xf, cln_g, cln_b,
                                     Wq, Wk, Wv, Wout, emb, Wemb);

    // 2) fused q/k/v projections + emb reduce + attention (producer-consumer flags)
    qkv_attn_kernel<<<1296, 256, GEMM_SMEM>>>(bq, bk, bv, bemb);

    // 3) modulate
    modulate_kernel<<<8192, 256>>>(sln_g, sln_b);

    // 4) output projection + residual
    outproj_gemm_kernel<<<dim3(8, 64), 256, GEMM_SMEM>>>(bout, x, out);
}